// round 1
// baseline (speedup 1.0000x reference)
#include <cuda_runtime.h>
#include <cstdint>

#define NSEG 10000
#define D    128

// Scratch: per-segment input sums (10000 x 128 fp32 = 5.12 MB).
__device__ float g_sums[NSEG * D];

// graph may be int32 or int64 depending on jax x64 config in the harness.
// Detect from the int32 word at index 2*NSEG-1:
//   int32 layout: that word is ends[NSEG-1] = N-1 (nonzero).
//   int64 layout: that word is the high half of element NSEG-1 (value < 2^31 -> 0).
__device__ __forceinline__ void load_seg(const int* __restrict__ g, int s,
                                         int& st, int& en) {
    bool is64 = (g[2 * NSEG - 1] == 0);
    if (is64) {
        const long long* g64 = (const long long*)g;
        st = (int)g64[2 * s];
        en = (int)g64[2 * s + 1];
    } else {
        st = g[2 * s];
        en = g[2 * s + 1];
    }
}

// Kernel A: sums[s][d] = sum over rows r in [start_s, end_s] of input[r][d].
// One block per segment, thread = column d. Coalesced 512B/row across block.
__global__ void __launch_bounds__(D) seg_sum_kernel(
    const float* __restrict__ input,
    const int*   __restrict__ graph)
{
    const int s   = blockIdx.x;
    const int tid = threadIdx.x;

    int start, end;
    load_seg(graph, s, start, end);

    const float* p = input + (long long)start * D + tid;
    const int n = end - start + 1;

    float acc = 0.0f;
    int r = 0;
    // Unroll 4 rows -> 4 independent LDGs in flight per thread.
    for (; r + 4 <= n; r += 4) {
        float a0 = p[0 * D];
        float a1 = p[1 * D];
        float a2 = p[2 * D];
        float a3 = p[3 * D];
        acc += (a0 + a1) + (a2 + a3);
        p += 4 * D;
    }
    for (; r < n; ++r) {
        acc += *p;
        p += D;
    }
    g_sums[s * D + tid] = acc;
}

// Kernel B: out[s][o] = dot(sums[s], W[o]) + count_s * b[o].
// One block per segment, thread = output column o. W rows read via float4
// (64 KB total, resident in L1 after first touch per SM).
__global__ void __launch_bounds__(D) seg_gemm_kernel(
    const int*   __restrict__ graph,
    const float* __restrict__ W,
    const float* __restrict__ b,
    float*       __restrict__ out)
{
    const int s = blockIdx.x;
    const int o = threadIdx.x;

    __shared__ float x[D];
    x[o] = g_sums[s * D + o];
    __syncthreads();

    const float4* Wr = (const float4*)(W + o * D);
    float acc = 0.0f;
#pragma unroll
    for (int d4 = 0; d4 < D / 4; ++d4) {
        float4 w = Wr[d4];
        // x[] indices uniform across the block -> smem broadcast, no conflicts.
        acc += w.x * x[4 * d4 + 0];
        acc += w.y * x[4 * d4 + 1];
        acc += w.z * x[4 * d4 + 2];
        acc += w.w * x[4 * d4 + 3];
    }

    int start, end;
    load_seg(graph, s, start, end);
    const float cnt = (float)(end - start + 1);

    out[s * D + o] = acc + cnt * b[o];
}

extern "C" void kernel_launch(void* const* d_in, const int* in_sizes, int n_in,
                              void* d_out, int out_size) {
    const float* input = (const float*)d_in[0];
    const int*   graph = (const int*)  d_in[1];
    const float* W     = (const float*)d_in[2];
    const float* b     = (const float*)d_in[3];
    float*       out   = (float*)d_out;

    seg_sum_kernel<<<NSEG, D>>>(input, graph);
    seg_gemm_kernel<<<NSEG, D>>>(graph, W, b, out);
}

// round 2
// speedup vs baseline: 2.5310x; 2.5310x over previous
#include <cuda_runtime.h>
#include <cstdint>

#define NSEG   10000
#define D      128
#define BM     64
#define BLK_B  256
#define XS_STRIDE 132   // pad so x broadcast reads hit distinct banks
#define SMEM_B ((D * D + BM * XS_STRIDE) * 4)   // 99328 bytes

// Scratch (no allocations allowed): per-segment sums + transposed W.
__device__ float g_sums[NSEG * D];
__device__ float g_WT[D * D];     // g_WT[k*D + n] = W[n*D + k]

// graph may be int32 or int64 depending on jax x64 config.
// int32 layout: word[2*NSEG-1] = ends[NSEG-1] = N-1 (nonzero).
// int64 layout: word[2*NSEG-1] = high half of element NSEG-1 -> 0.
__device__ __forceinline__ void load_seg(const int* __restrict__ g, int s,
                                         int& st, int& en) {
    bool is64 = (g[2 * NSEG - 1] == 0);
    if (is64) {
        const long long* g64 = (const long long*)g;
        st = (int)g64[2 * s];
        en = (int)g64[2 * s + 1];
    } else {
        st = g[2 * s];
        en = g[2 * s + 1];
    }
}

// ---------------------------------------------------------------------------
// Kernel T: transpose W (128x128, 64KB) into g_WT. Trivial cost.
// block k (128 blocks), thread n: g_WT[k][n] = W[n][k]. Writes coalesced.
// ---------------------------------------------------------------------------
__global__ void __launch_bounds__(D) wt_kernel(const float* __restrict__ W) {
    int k = blockIdx.x;
    int n = threadIdx.x;
    g_WT[k * D + n] = W[n * D + k];
}

// ---------------------------------------------------------------------------
// Kernel A: sums[s][:] = sum of input rows in [start_s, end_s].
// One block per segment. Warp rl (0..3) handles rows start+rl, +4, ...
// each lane loads one float4 of the 512B row -> 1 LDG.128 warp-instr per row.
// ---------------------------------------------------------------------------
__global__ void __launch_bounds__(128) seg_sum_kernel(
    const float* __restrict__ input,
    const int*   __restrict__ graph)
{
    const int s   = blockIdx.x;
    const int c4  = threadIdx.x & 31;   // float4 column within row
    const int rl  = threadIdx.x >> 5;   // row lane 0..3

    int start, end;
    load_seg(graph, s, start, end);
    const int n = end - start + 1;

    const float4* p = (const float4*)input + (long long)(start + rl) * 32 + c4;

    float4 acc = make_float4(0.f, 0.f, 0.f, 0.f);
    int r = rl;
    // 2-row unroll: two independent LDG.128 in flight.
    for (; r + 4 < n; r += 8) {
        float4 v0 = p[0];
        float4 v1 = p[128];       // +4 rows = 4*32 float4
        acc.x += v0.x + v1.x;
        acc.y += v0.y + v1.y;
        acc.z += v0.z + v1.z;
        acc.w += v0.w + v1.w;
        p += 256;
    }
    if (r < n) {
        float4 v = p[0];
        acc.x += v.x; acc.y += v.y; acc.z += v.z; acc.w += v.w;
    }

    __shared__ float4 red[4][32];
    red[rl][c4] = acc;
    __syncthreads();
    if (rl == 0) {
        float4 a = red[0][c4], b2 = red[1][c4], c = red[2][c4], d = red[3][c4];
        float4 t;
        t.x = (a.x + b2.x) + (c.x + d.x);
        t.y = (a.y + b2.y) + (c.y + d.y);
        t.z = (a.z + b2.z) + (c.z + d.z);
        t.w = (a.w + b2.w) + (c.w + d.w);
        ((float4*)g_sums)[s * 32 + c4] = t;
    }
}

// ---------------------------------------------------------------------------
// Kernel B: out[m][n] = sum_k xs[m][k] * WT[k][n] + cnt_m * b[n]
// Register-blocked GEMM: BM=64 segments per block, 256 threads,
// thread (ty,tx) computes 4 m's x 8 n's. smem: ws[k][n] 64KB (from g_WT,
// copy is layout-identical -> conflict-free), xs[m][k] padded to stride 132.
// ---------------------------------------------------------------------------
__global__ void __launch_bounds__(BLK_B) seg_gemm_kernel(
    const int*   __restrict__ graph,
    const float* __restrict__ b,
    float*       __restrict__ out)
{
    extern __shared__ float sm[];
    float* ws = sm;            // ws[k*D + n]
    float* xs = sm + D * D;    // xs[m*XS_STRIDE + k]

    const int tid = threadIdx.x;
    const int m0  = blockIdx.x * BM;

    // Stage W^T: straight copy (same layout), coalesced, conflict-free.
    {
        const float4* src = (const float4*)g_WT;
#pragma unroll
        for (int i = 0; i < (D * D / 4) / BLK_B; i++) {    // 16 iters
            int lin = tid + i * BLK_B;
            ((float4*)ws)[lin] = src[lin];
        }
    }
    // Stage x tile: natural [m][k] layout, coalesced float4 reads/writes.
    {
#pragma unroll
        for (int i = 0; i < (BM * D / 4) / BLK_B; i++) {   // 8 iters
            int lin = tid + i * BLK_B;
            int m   = lin >> 5;        // 32 float4 per row
            int k4  = lin & 31;
            int seg = m0 + m;
            float4 v = make_float4(0.f, 0.f, 0.f, 0.f);
            if (seg < NSEG) v = ((const float4*)g_sums)[seg * 32 + k4];
            *(float4*)(xs + m * XS_STRIDE + k4 * 4) = v;
        }
    }
    __syncthreads();

    const int tx = tid & 15;    // n-group: n = tx*8 .. tx*8+7
    const int ty = tid >> 4;    // m-group: m = ty*4 .. ty*4+3

    float acc[4][8];
#pragma unroll
    for (int i = 0; i < 4; i++)
#pragma unroll
        for (int j = 0; j < 8; j++) acc[i][j] = 0.f;

    const float* xp0 = xs + (ty * 4 + 0) * XS_STRIDE;
    const float* xp1 = xs + (ty * 4 + 1) * XS_STRIDE;
    const float* xp2 = xs + (ty * 4 + 2) * XS_STRIDE;
    const float* xp3 = xs + (ty * 4 + 3) * XS_STRIDE;
    const float* wp  = ws + tx * 8;

#pragma unroll 8
    for (int k = 0; k < D; k++) {
        float4 w0 = *(const float4*)(wp + k * D);
        float4 w1 = *(const float4*)(wp + k * D + 4);
        float x0 = xp0[k], x1 = xp1[k], x2 = xp2[k], x3 = xp3[k];

        acc[0][0] += x0 * w0.x; acc[0][1] += x0 * w0.y;
        acc[0][2] += x0 * w0.z; acc[0][3] += x0 * w0.w;
        acc[0][4] += x0 * w1.x; acc[0][5] += x0 * w1.y;
        acc[0][6] += x0 * w1.z; acc[0][7] += x0 * w1.w;

        acc[1][0] += x1 * w0.x; acc[1][1] += x1 * w0.y;
        acc[1][2] += x1 * w0.z; acc[1][3] += x1 * w0.w;
        acc[1][4] += x1 * w1.x; acc[1][5] += x1 * w1.y;
        acc[1][6] += x1 * w1.z; acc[1][7] += x1 * w1.w;

        acc[2][0] += x2 * w0.x; acc[2][1] += x2 * w0.y;
        acc[2][2] += x2 * w0.z; acc[2][3] += x2 * w0.w;
        acc[2][4] += x2 * w1.x; acc[2][5] += x2 * w1.y;
        acc[2][6] += x2 * w1.z; acc[2][7] += x2 * w1.w;

        acc[3][0] += x3 * w0.x; acc[3][1] += x3 * w0.y;
        acc[3][2] += x3 * w0.z; acc[3][3] += x3 * w0.w;
        acc[3][4] += x3 * w1.x; acc[3][5] += x3 * w1.y;
        acc[3][6] += x3 * w1.z; acc[3][7] += x3 * w1.w;
    }

    // Epilogue: + count * b, vectorized stores.
    float4 b0 = ((const float4*)b)[tx * 2];
    float4 b1 = ((const float4*)b)[tx * 2 + 1];

#pragma unroll
    for (int i = 0; i < 4; i++) {
        int seg = m0 + ty * 4 + i;
        if (seg >= NSEG) continue;
        int st, en;
        load_seg(graph, seg, st, en);
        float cnt = (float)(en - st + 1);

        float4 o0, o1;
        o0.x = acc[i][0] + cnt * b0.x;
        o0.y = acc[i][1] + cnt * b0.y;
        o0.z = acc[i][2] + cnt * b0.z;
        o0.w = acc[i][3] + cnt * b0.w;
        o1.x = acc[i][4] + cnt * b1.x;
        o1.y = acc[i][5] + cnt * b1.y;
        o1.z = acc[i][6] + cnt * b1.z;
        o1.w = acc[i][7] + cnt * b1.w;

        float4* op = (float4*)(out + (long long)seg * D + tx * 8);
        op[0] = o0;
        op[1] = o1;
    }
}

extern "C" void kernel_launch(void* const* d_in, const int* in_sizes, int n_in,
                              void* d_out, int out_size) {
    const float* input = (const float*)d_in[0];
    const int*   graph = (const int*)  d_in[1];
    const float* W     = (const float*)d_in[2];
    const float* b     = (const float*)d_in[3];
    float*       out   = (float*)d_out;

    cudaFuncSetAttribute(seg_gemm_kernel,
                         cudaFuncAttributeMaxDynamicSharedMemorySize, SMEM_B);

    wt_kernel<<<D, D>>>(W);
    seg_sum_kernel<<<NSEG, 128>>>(input, graph);
    seg_gemm_kernel<<<(NSEG + BM - 1) / BM, BLK_B, SMEM_B>>>(graph, b, out);
}